// round 14
// baseline (speedup 1.0000x reference)
#include <cuda_runtime.h>
#include <cuda_bf16.h>
#include <math.h>
#include <stdint.h>

#define NH    32
#define LLEN  4096
#define BSTRIDE 144   // bytes per b-row in smem B (64 bf16 + 16B pad)

struct C2 { float r, i; };

static __device__ __forceinline__ C2 cmul(C2 a, C2 b) {
    return { a.r * b.r - a.i * b.i, a.r * b.i + a.i * b.r };
}

// fp32 phase reduction: exact Dekker product + 3-term Cody-Waite (R6-proven)
static __device__ __forceinline__ float reduce2pi(float yi, float lf) {
    const float INV2PI = 0.15915494309189534f;
    const float PI2_A  = 6.28125f;
    const float PI2_B  = 1.93500518798828125e-3f;
    const float PI2_C  = 3.0199159819568e-7f;
    const float p  = yi * lf;
    const float pe = fmaf(yi, lf, -p);
    const float k  = rintf(p * INV2PI);
    const float t0 = fmaf(-k, PI2_A, p);
    const float t1 = fmaf(-k, PI2_B, t0);
    return fmaf(-k, PI2_C, t1) + pe;
}

static __device__ __forceinline__ C2 zpow(float xr, float yi, float lf) {
    const float red = reduce2pi(yi, lf);
    float sf, cf;
    __sincosf(red, &sf, &cf);
    const float ef = __expf(xr * lf);
    return { ef * cf, ef * sf };
}

// split (v0,v1) into bf16 hi pair + lo pair using packed cvt + bit-trick residual
static __device__ __forceinline__ void split_pack(float v0, float v1,
                                                  uint32_t& hi, uint32_t& lo) {
    uint32_t hp;
    asm("cvt.rn.bf16x2.f32 %0, %1, %2;" : "=r"(hp) : "f"(v1), "f"(v0)); // lo16=v0
    const float f0 = __uint_as_float(hp << 16);
    const float f1 = __uint_as_float(hp & 0xFFFF0000u);
    const float r0 = v0 - f0;
    const float r1 = v1 - f1;
    asm("cvt.rn.bf16x2.f32 %0, %1, %2;" : "=r"(lo) : "f"(r1), "f"(r0));
    hi = hp;
}

static __device__ __forceinline__ void mma16816(
    float& d0, float& d1, float& d2, float& d3,
    uint32_t a0, uint32_t a1, uint32_t a2, uint32_t a3,
    uint32_t b0, uint32_t b1)
{
    asm volatile(
        "mma.sync.aligned.m16n8k16.row.col.f32.bf16.bf16.f32 "
        "{%0,%1,%2,%3}, {%4,%5,%6,%7}, {%8,%9}, {%0,%1,%2,%3};"
        : "+f"(d0), "+f"(d1), "+f"(d2), "+f"(d3)
        : "r"(a0), "r"(a1), "r"(a2), "r"(a3), "r"(b0), "r"(b1));
}

__global__ __launch_bounds__(256, 4) void s4d_mma_kernel(
    const float* __restrict__ log_dt,
    const float* __restrict__ C_real,
    const float* __restrict__ log_A_real,
    const float* __restrict__ A_imag,
    float* __restrict__ out)
{
    __shared__ float sxr[NH], syi[NH], scdr[NH], scdi[NH];
    // anchor tables: [0]=z^i, [1]=Cd*z^(8j), [2]=z^(64i), [3]=z^(512j)
    __shared__ __align__(16) float2 sTab[4][NH][8];                // 8 KB
    // B (hi,lo) [b][k] bf16 rows of 144B; overlaid later by Dt[64][68] f32
    __shared__ __align__(16) unsigned char sB[2 * 64 * BSTRIDE];   // 18432 B

    const int h   = blockIdx.x;
    const int tid = threadIdx.x;

    // ---- phase 1: per-(h,n) scalars (warp 0) ---------------------------------
    if (tid < NH) {
        const int n = tid;
        const float dt  = expf(log_dt[h]);
        const float Arf = -expf(log_A_real[h * NH + n]);
        const float Aif = A_imag[h * NH + n];
        const float xr  = dt * Arf;          // matches reference f32 product
        const float yi  = dt * Aif;

        const float em1 = expm1f(xr);
        float sy, cy;
        sincosf(yi, &sy, &cy);
        const float sh   = sinf(0.5f * yi);
        const float numr = em1 * cy - 2.0f * sh * sh;   // e^x cos y - 1
        const float numi = (1.0f + em1) * sy;           // e^x sin y
        const float invd = 1.0f / (Arf * Arf + Aif * Aif);
        const float tr = (numr * Arf + numi * Aif) * invd;
        const float ti = (numi * Arf - numr * Aif) * invd;
        const float Cr = C_real[(h * NH + n) * 2 + 0];
        const float Ci = C_real[(h * NH + n) * 2 + 1];
        scdr[n] = 2.0f * (Cr * tr - Ci * ti);
        scdi[n] = 2.0f * (Cr * ti + Ci * tr);
        sxr[n] = xr;
        syi[n] = yi;
    }
    __syncthreads();

    // ---- phase 2: anchor tables, 4 independent zpow per thread ---------------
    {
        #pragma unroll
        for (int q = 0; q < 4; q++) {
            const int f   = q * 256 + tid;     // 0..1023
            const int tab = f >> 8;            // 0..3
            const int sub = f & 255;
            const int n   = sub >> 3;
            const int i   = sub & 7;
            const int mul = (tab == 0) ? 1 : (tab == 1) ? 8 : (tab == 2) ? 64 : 512;
            C2 zv = zpow(sxr[n], syi[n], (float)(mul * i));
            if (tab == 1) zv = cmul(C2{ scdr[n], scdi[n] }, zv);
            sTab[tab][n][i] = make_float2(zv.r, zv.i);
        }
    }
    __syncthreads();

    // ---- B producer: thread -> rows (bl, bl+32) x 4 n, pure cmul -------------
    {
        const int bl = tid & 31;
        const int g  = tid >> 5;           // 0..7
        const int nb = 4 * g;
        const int bi = bl & 7;
        const int bj = bl >> 3;
        unsigned char* Bh = sB;
        unsigned char* Bl = sB + 64 * BSTRIDE;
        uint32_t h0v[4], l0v[4], h1v[4], l1v[4];
        #pragma unroll
        for (int j = 0; j < 4; j++) {
            const int n = nb + j;
            const float2 tc  = sTab[2][n][bi];
            const float2 td  = sTab[3][n][bj];
            const float2 td2 = sTab[3][n][bj + 4];
            const C2 q  = cmul(C2{ td.x,  td.y  }, C2{ tc.x, tc.y });  // z^(64*bl)
            const C2 qh = cmul(C2{ td2.x, td2.y }, C2{ tc.x, tc.y });  // z^(64*(bl+32))
            split_pack(q.r,  q.i,  h0v[j], l0v[j]);
            split_pack(qh.r, qh.i, h1v[j], l1v[j]);
        }
        const uint32_t off  = (uint32_t)(bl * BSTRIDE + 4 * nb);
        const uint32_t off2 = (uint32_t)((bl + 32) * BSTRIDE + 4 * nb);
        *(uint4*)(Bh + off)  = *(uint4*)h0v;
        *(uint4*)(Bl + off)  = *(uint4*)l0v;
        *(uint4*)(Bh + off2) = *(uint4*)h1v;
        *(uint4*)(Bl + off2) = *(uint4*)l1v;
    }
    __syncthreads();

    // ---- MMA mainloop: kt outer; warp-groups split nt ------------------------
    const int wid  = tid >> 5;
    const int wrow = wid & 3;      // rows 16*wrow .. +15
    const int wcol = wid >> 2;     // 0: nt 0-3 (b 0-31), 1: nt 4-7 (b 32-63)
    const int r = (tid >> 2) & 7;  // lane/4
    const int t = tid & 3;         // lane%4

    float d[4][4];
    #pragma unroll
    for (int nt = 0; nt < 4; nt++)
        #pragma unroll
        for (int c = 0; c < 4; c++) d[nt][c] = 0.0f;

    const unsigned char* Bh  = sB;
    const unsigned char* Blo = sB + 64 * BSTRIDE;

    #pragma unroll
    for (int kt = 0; kt < 4; kt++) {
        // A fragments for this kt from tables (duplicated across wcol: cheap cmul)
        uint32_t Ah[4], Al[4];
        #pragma unroll
        for (int s = 0; s < 2; s++) {
            const int n = 8 * kt + t + 4 * s;
            const float2 ta  = sTab[0][n][r];          // z^r
            const float2 tb0 = sTab[1][n][2 * wrow];   // Cd*z^(16*wrow)
            const float2 tb1 = sTab[1][n][2 * wrow + 1];
            const C2 p  = cmul(C2{ tb0.x, tb0.y }, C2{ ta.x, ta.y });  // Cd*z^a
            const C2 ph = cmul(C2{ tb1.x, tb1.y }, C2{ ta.x, ta.y });  // Cd*z^(a+8)
            split_pack(p.r,  -p.i,  Ah[0 + 2 * s], Al[0 + 2 * s]);
            split_pack(ph.r, -ph.i, Ah[1 + 2 * s], Al[1 + 2 * s]);
        }
        #pragma unroll
        for (int nt = 0; nt < 4; nt++) {
            const int ntg = 4 * wcol + nt;
            const uint32_t off = (uint32_t)((8 * ntg + r) * BSTRIDE + 4 * t + 32 * kt);
            const uint32_t bh0 = *(const uint32_t*)(Bh  + off);
            const uint32_t bh1 = *(const uint32_t*)(Bh  + off + 16);
            const uint32_t bl0 = *(const uint32_t*)(Blo + off);
            const uint32_t bl1 = *(const uint32_t*)(Blo + off + 16);
            mma16816(d[nt][0], d[nt][1], d[nt][2], d[nt][3],
                     Ah[0], Ah[1], Ah[2], Ah[3], bh0, bh1);
            mma16816(d[nt][0], d[nt][1], d[nt][2], d[nt][3],
                     Ah[0], Ah[1], Ah[2], Ah[3], bl0, bl1);
            mma16816(d[nt][0], d[nt][1], d[nt][2], d[nt][3],
                     Al[0], Al[1], Al[2], Al[3], bh0, bh1);
        }
    }
    __syncthreads();   // all B reads done before Dt overlay

    // ---- stage D[a][b] -> Dt[b][a] (pad 68 words: conflict-free writes) ------
    float (*Dt)[68] = reinterpret_cast<float(*)[68]>(sB);
    {
        const int ar = 16 * wrow + r;
        #pragma unroll
        for (int nt = 0; nt < 4; nt++) {
            const int bc = 8 * (4 * wcol + nt) + 2 * t;
            Dt[bc    ][ar    ] = d[nt][0];
            Dt[bc + 1][ar    ] = d[nt][1];
            Dt[bc    ][ar + 8] = d[nt][2];
            Dt[bc + 1][ar + 8] = d[nt][3];
        }
    }
    __syncthreads();

    // ---- coalesced vector store: out[h][b*64+a] ------------------------------
    float* outh = out + (size_t)h * LLEN;
    #pragma unroll
    for (int it = 0; it < 4; it++) {
        const int idx = it * 1024 + tid * 4;
        const float4 v = *(const float4*)&Dt[idx >> 6][idx & 63];
        *(float4*)&outh[idx] = v;
    }
}

extern "C" void kernel_launch(void* const* d_in, const int* in_sizes, int n_in,
                              void* d_out, int out_size)
{
    const float* log_dt     = (const float*)d_in[0];
    const float* C_real     = (const float*)d_in[1];
    const float* log_A_real = (const float*)d_in[2];
    const float* A_imag     = (const float*)d_in[3];
    float* out = (float*)d_out;
    s4d_mma_kernel<<<1024, 256>>>(log_dt, C_real, log_A_real, A_imag, out);
}

// round 15
// speedup vs baseline: 1.0737x; 1.0737x over previous
#include <cuda_runtime.h>
#include <cuda_bf16.h>
#include <math.h>
#include <stdint.h>

#define NH    32
#define LLEN  4096
#define BSTRIDE 144   // bytes per b-row in smem B (64 bf16 + 16B pad)

struct C2 { float r, i; };

static __device__ __forceinline__ C2 cmul(C2 a, C2 b) {
    return { a.r * b.r - a.i * b.i, a.r * b.i + a.i * b.r };
}

// fp32 phase reduction: exact Dekker product + 3-term Cody-Waite (R6-proven)
static __device__ __forceinline__ float reduce2pi(float yi, float lf) {
    const float INV2PI = 0.15915494309189534f;
    const float PI2_A  = 6.28125f;
    const float PI2_B  = 1.93500518798828125e-3f;
    const float PI2_C  = 3.0199159819568e-7f;
    const float p  = yi * lf;
    const float pe = fmaf(yi, lf, -p);
    const float k  = rintf(p * INV2PI);
    const float t0 = fmaf(-k, PI2_A, p);
    const float t1 = fmaf(-k, PI2_B, t0);
    return fmaf(-k, PI2_C, t1) + pe;
}

static __device__ __forceinline__ C2 zpow(float xr, float yi, float lf) {
    const float red = reduce2pi(yi, lf);
    float sf, cf;
    __sincosf(red, &sf, &cf);
    const float ef = __expf(xr * lf);
    return { ef * cf, ef * sf };
}

// split (v0,v1) into bf16 hi pair + lo pair using packed cvt + bit-trick residual
static __device__ __forceinline__ void split_pack(float v0, float v1,
                                                  uint32_t& hi, uint32_t& lo) {
    uint32_t hp;
    asm("cvt.rn.bf16x2.f32 %0, %1, %2;" : "=r"(hp) : "f"(v1), "f"(v0)); // lo16=v0
    const float f0 = __uint_as_float(hp << 16);
    const float f1 = __uint_as_float(hp & 0xFFFF0000u);
    const float r0 = v0 - f0;
    const float r1 = v1 - f1;
    asm("cvt.rn.bf16x2.f32 %0, %1, %2;" : "=r"(lo) : "f"(r1), "f"(r0));
    hi = hp;
}

static __device__ __forceinline__ void mma16816(
    float& d0, float& d1, float& d2, float& d3,
    uint32_t a0, uint32_t a1, uint32_t a2, uint32_t a3,
    uint32_t b0, uint32_t b1)
{
    asm volatile(
        "mma.sync.aligned.m16n8k16.row.col.f32.bf16.bf16.f32 "
        "{%0,%1,%2,%3}, {%4,%5,%6,%7}, {%8,%9}, {%0,%1,%2,%3};"
        : "+f"(d0), "+f"(d1), "+f"(d2), "+f"(d3)
        : "r"(a0), "r"(a1), "r"(a2), "r"(a3), "r"(b0), "r"(b1));
}

__global__ __launch_bounds__(128, 8) void s4d_mma_kernel(
    const float* __restrict__ log_dt,
    const float* __restrict__ C_real,
    const float* __restrict__ log_A_real,
    const float* __restrict__ A_imag,
    float* __restrict__ out)
{
    __shared__ float sxr[NH], syi[NH], scdr[NH], scdi[NH];
    // anchor tables: [0]=z^i, [1]=Cd*z^(8j), [2]=z^(64i), [3]=z^(512j)
    __shared__ __align__(16) float2 sTab[4][NH][8];                // 8 KB
    // B (hi,lo) [b][k] bf16 rows of 144B; overlaid later by Dt[64][68] f32
    __shared__ __align__(16) unsigned char sB[2 * 64 * BSTRIDE];   // 18432 B

    const int h   = blockIdx.x;
    const int tid = threadIdx.x;

    // ---- phase 1: per-(h,n) scalars, straight-line fast math (warp 0) --------
    if (tid < NH) {
        const int n = tid;
        const float dt  = expf(log_dt[h]);               // accuracy-critical
        const float Arf = -__expf(log_A_real[h * NH + n]);  // |log_A|=log2: safe fast
        const float Aif = A_imag[h * NH + n];
        const float xr  = dt * Arf;          // matches reference f32 product
        const float yi  = dt * Aif;          // |yi| <= 0.1*pi*31 ~ 9.74

        // e^x - 1, x in [-0.0503, 0): 4-term Taylor, rel tail ~ x^4/120 < 3e-9
        const float em1 = xr * fmaf(xr, fmaf(xr, fmaf(xr, 1.0f/24.0f, 1.0f/6.0f), 0.5f), 1.0f);
        // sin/cos of yi via proven reduction; versine = 1-cos = 2 sin^2(red/2)
        const float red = reduce2pi(yi, 1.0f);
        float sy, cy;
        __sincosf(red, &sy, &cy);
        const float sh   = __sinf(0.5f * red);
        const float numr = em1 * cy - 2.0f * sh * sh;   // e^x cos y - 1
        const float numi = (1.0f + em1) * sy;           // e^x sin y
        const float invd = 1.0f / (Arf * Arf + Aif * Aif);
        const float tr = (numr * Arf + numi * Aif) * invd;
        const float ti = (numi * Arf - numr * Aif) * invd;
        const float Cr = C_real[(h * NH + n) * 2 + 0];
        const float Ci = C_real[(h * NH + n) * 2 + 1];
        scdr[n] = 2.0f * (Cr * tr - Ci * ti);
        scdi[n] = 2.0f * (Cr * ti + Ci * tr);
        sxr[n] = xr;
        syi[n] = yi;
    }
    __syncthreads();

    // ---- phase 2: anchor tables, 8 independent zpow per thread ---------------
    {
        #pragma unroll
        for (int q = 0; q < 8; q++) {
            const int f   = q * 128 + tid;     // 0..1023
            const int tab = f >> 8;            // 0..3
            const int sub = f & 255;
            const int n   = sub >> 3;
            const int i   = sub & 7;
            const int mul = (tab == 0) ? 1 : (tab == 1) ? 8 : (tab == 2) ? 64 : 512;
            C2 zv = zpow(sxr[n], syi[n], (float)(mul * i));
            if (tab == 1) zv = cmul(C2{ scdr[n], scdi[n] }, zv);
            sTab[tab][n][i] = make_float2(zv.r, zv.i);
        }
    }
    __syncthreads();

    // ---- B producer: thread -> (b=lane, b=lane+32) x 8 n, pure cmul ----------
    {
        const int bl = tid & 31;
        const int nb = (tid >> 5) * 8;
        const int bi = bl & 7;
        const int bj = bl >> 3;
        unsigned char* Bh = sB;
        unsigned char* Bl = sB + 64 * BSTRIDE;
        uint32_t h0v[8], l0v[8], h1v[8], l1v[8];
        #pragma unroll
        for (int j = 0; j < 8; j++) {
            const int n = nb + j;
            const float2 tc  = sTab[2][n][bi];
            const float2 td  = sTab[3][n][bj];
            const float2 td2 = sTab[3][n][bj + 4];
            const C2 q  = cmul(C2{ td.x,  td.y  }, C2{ tc.x, tc.y });  // z^(64*bl)
            const C2 qh = cmul(C2{ td2.x, td2.y }, C2{ tc.x, tc.y });  // z^(64*(bl+32))
            split_pack(q.r,  q.i,  h0v[j], l0v[j]);
            split_pack(qh.r, qh.i, h1v[j], l1v[j]);
        }
        const uint32_t off  = (uint32_t)(bl * BSTRIDE + 4 * nb);
        const uint32_t off2 = (uint32_t)((bl + 32) * BSTRIDE + 4 * nb);
        *(uint4*)(Bh + off)       = *(uint4*)(h0v);
        *(uint4*)(Bh + off + 16)  = *(uint4*)(h0v + 4);
        *(uint4*)(Bl + off)       = *(uint4*)(l0v);
        *(uint4*)(Bl + off + 16)  = *(uint4*)(l0v + 4);
        *(uint4*)(Bh + off2)      = *(uint4*)(h1v);
        *(uint4*)(Bh + off2 + 16) = *(uint4*)(h1v + 4);
        *(uint4*)(Bl + off2)      = *(uint4*)(l1v);
        *(uint4*)(Bl + off2 + 16) = *(uint4*)(l1v + 4);
    }
    __syncthreads();

    // ---- MMA mainloop: kt outer; B frags double-buffered over nt -------------
    const int w = tid >> 5;        // warp -> rows 16w..16w+15
    const int r = (tid >> 2) & 7;  // lane/4
    const int t = tid & 3;         // lane%4

    float d[8][4];
    #pragma unroll
    for (int nt = 0; nt < 8; nt++)
        #pragma unroll
        for (int c = 0; c < 4; c++) d[nt][c] = 0.0f;

    const unsigned char* Bh  = sB;
    const unsigned char* Blo = sB + 64 * BSTRIDE;

    #pragma unroll
    for (int kt = 0; kt < 4; kt++) {
        // A fragments for this kt from tables (2 cmul + 2 split per s)
        uint32_t Ah[4], Al[4];
        #pragma unroll
        for (int s = 0; s < 2; s++) {
            const int n = 8 * kt + t + 4 * s;
            const float2 ta  = sTab[0][n][r];          // z^r
            const float2 tb0 = sTab[1][n][2 * w];      // Cd*z^(16w)
            const float2 tb1 = sTab[1][n][2 * w + 1];  // Cd*z^(16w+8)
            const C2 p  = cmul(C2{ tb0.x, tb0.y }, C2{ ta.x, ta.y });  // Cd*z^a
            const C2 ph = cmul(C2{ tb1.x, tb1.y }, C2{ ta.x, ta.y });  // Cd*z^(a+8)
            split_pack(p.r,  -p.i,  Ah[0 + 2 * s], Al[0 + 2 * s]);
            split_pack(ph.r, -ph.i, Ah[1 + 2 * s], Al[1 + 2 * s]);
        }
        // double-buffered B fragment loads across nt
        uint32_t bh0, bh1, bl0, bl1;
        {
            const uint32_t off0 = (uint32_t)(r * BSTRIDE + 4 * t + 32 * kt);
            bh0 = *(const uint32_t*)(Bh  + off0);
            bh1 = *(const uint32_t*)(Bh  + off0 + 16);
            bl0 = *(const uint32_t*)(Blo + off0);
            bl1 = *(const uint32_t*)(Blo + off0 + 16);
        }
        #pragma unroll
        for (int nt = 0; nt < 8; nt++) {
            uint32_t nh0, nh1, nl0, nl1;
            if (nt < 7) {
                const uint32_t offn = (uint32_t)((8 * (nt + 1) + r) * BSTRIDE + 4 * t + 32 * kt);
                nh0 = *(const uint32_t*)(Bh  + offn);
                nh1 = *(const uint32_t*)(Bh  + offn + 16);
                nl0 = *(const uint32_t*)(Blo + offn);
                nl1 = *(const uint32_t*)(Blo + offn + 16);
            }
            mma16816(d[nt][0], d[nt][1], d[nt][2], d[nt][3],
                     Ah[0], Ah[1], Ah[2], Ah[3], bh0, bh1);
            mma16816(d[nt][0], d[nt][1], d[nt][2], d[nt][3],
                     Ah[0], Ah[1], Ah[2], Ah[3], bl0, bl1);
            mma16816(d[nt][0], d[nt][1], d[nt][2], d[nt][3],
                     Al[0], Al[1], Al[2], Al[3], bh0, bh1);
            if (nt < 7) { bh0 = nh0; bh1 = nh1; bl0 = nl0; bl1 = nl1; }
        }
    }
    __syncthreads();   // all B reads done before Dt overlay

    // ---- stage D[a][b] -> Dt[b][a] (pad 68 words: conflict-free writes) ------
    float (*Dt)[68] = reinterpret_cast<float(*)[68]>(sB);
    {
        const int ar = 16 * w + r;
        #pragma unroll
        for (int nt = 0; nt < 8; nt++) {
            const int bc = 8 * nt + 2 * t;
            Dt[bc    ][ar    ] = d[nt][0];
            Dt[bc + 1][ar    ] = d[nt][1];
            Dt[bc    ][ar + 8] = d[nt][2];
            Dt[bc + 1][ar + 8] = d[nt][3];
        }
    }
    __syncthreads();

    // ---- coalesced vector store: out[h][b*64+a] ------------------------------
    float* outh = out + (size_t)h * LLEN;
    #pragma unroll
    for (int it = 0; it < 8; it++) {
        const int idx = it * 512 + tid * 4;
        const float4 v = *(const float4*)&Dt[idx >> 6][idx & 63];
        *(float4*)&outh[idx] = v;
    }
}

extern "C" void kernel_launch(void* const* d_in, const int* in_sizes, int n_in,
                              void* d_out, int out_size)
{
    const float* log_dt     = (const float*)d_in[0];
    const float* C_real     = (const float*)d_in[1];
    const float* log_A_real = (const float*)d_in[2];
    const float* A_imag     = (const float*)d_in[3];
    float* out = (float*)d_out;
    s4d_mma_kernel<<<1024, 128>>>(log_dt, C_real, log_A_real, A_imag, out);
}

// round 16
// speedup vs baseline: 1.2526x; 1.1667x over previous
#include <cuda_runtime.h>
#include <cuda_bf16.h>
#include <math.h>
#include <stdint.h>

#define NH    32
#define NHP   34      // padded n-dim for tables (bank spread)
#define LLEN  4096
#define BSTRIDE 144   // bytes per b-row in smem B (64 bf16 + 16B pad)

struct C2 { float r, i; };

static __device__ __forceinline__ C2 cmul(C2 a, C2 b) {
    return { a.r * b.r - a.i * b.i, a.r * b.i + a.i * b.r };
}

// fp32 phase reduction: exact Dekker product + 3-term Cody-Waite (R6-proven)
static __device__ __forceinline__ float reduce2pi(float yi, float lf) {
    const float INV2PI = 0.15915494309189534f;
    const float PI2_A  = 6.28125f;
    const float PI2_B  = 1.93500518798828125e-3f;
    const float PI2_C  = 3.0199159819568e-7f;
    const float p  = yi * lf;
    const float pe = fmaf(yi, lf, -p);
    const float k  = rintf(p * INV2PI);
    const float t0 = fmaf(-k, PI2_A, p);
    const float t1 = fmaf(-k, PI2_B, t0);
    return fmaf(-k, PI2_C, t1) + pe;
}

static __device__ __forceinline__ C2 zpow(float xr, float yi, float lf) {
    const float red = reduce2pi(yi, lf);
    float sf, cf;
    __sincosf(red, &sf, &cf);
    const float ef = __expf(xr * lf);
    return { ef * cf, ef * sf };
}

// split (v0,v1) into bf16 hi pair + lo pair using packed cvt + bit-trick residual
static __device__ __forceinline__ void split_pack(float v0, float v1,
                                                  uint32_t& hi, uint32_t& lo) {
    uint32_t hp;
    asm("cvt.rn.bf16x2.f32 %0, %1, %2;" : "=r"(hp) : "f"(v1), "f"(v0)); // lo16=v0
    const float f0 = __uint_as_float(hp << 16);
    const float f1 = __uint_as_float(hp & 0xFFFF0000u);
    const float r0 = v0 - f0;
    const float r1 = v1 - f1;
    asm("cvt.rn.bf16x2.f32 %0, %1, %2;" : "=r"(lo) : "f"(r1), "f"(r0));
    hi = hp;
}

static __device__ __forceinline__ void mma16816(
    float& d0, float& d1, float& d2, float& d3,
    uint32_t a0, uint32_t a1, uint32_t a2, uint32_t a3,
    uint32_t b0, uint32_t b1)
{
    asm volatile(
        "mma.sync.aligned.m16n8k16.row.col.f32.bf16.bf16.f32 "
        "{%0,%1,%2,%3}, {%4,%5,%6,%7}, {%8,%9}, {%0,%1,%2,%3};"
        : "+f"(d0), "+f"(d1), "+f"(d2), "+f"(d3)
        : "r"(a0), "r"(a1), "r"(a2), "r"(a3), "r"(b0), "r"(b1));
}

__global__ __launch_bounds__(128, 8) void s4d_mma_kernel(
    const float* __restrict__ log_dt,
    const float* __restrict__ C_real,
    const float* __restrict__ log_A_real,
    const float* __restrict__ A_imag,
    float* __restrict__ out)
{
    // tables [tab][i][n]: 0: z^i, 1: Cd*z^(8j), 2: z^(64i), 3: z^(512j)
    __shared__ __align__(16) float2 sTab[4][8][NHP];               // 8704 B
    // B (hi,lo) [b][k] bf16 rows of 144B; overlaid later by Dt[64][68] f32
    __shared__ __align__(16) unsigned char sB[2 * 64 * BSTRIDE];   // 18432 B

    const int h   = blockIdx.x;
    const int tid = threadIdx.x;
    const int wid  = tid >> 5;
    const int lane = tid & 31;

    // ---- merged phase 1+2: lane n scalars (x4 redundant), warp w builds table w
    {
        const int n = lane;
        const float dt  = expf(log_dt[h]);                 // accuracy-critical
        const float Arf = -__expf(log_A_real[h * NH + n]);
        const float Aif = A_imag[h * NH + n];
        const float xr  = dt * Arf;           // matches reference f32 product
        const float yi  = dt * Aif;

        // e^x - 1, x in [-0.0503, 0): Taylor, rel tail < 3e-9
        const float em1 = xr * fmaf(xr, fmaf(xr, fmaf(xr, 1.0f/24.0f, 1.0f/6.0f), 0.5f), 1.0f);
        const float red = reduce2pi(yi, 1.0f);
        float sy, cy;
        __sincosf(red, &sy, &cy);
        const float ex = 1.0f + em1;
        const C2 z = { ex * cy, ex * sy };                 // z = e^{dtA}, free

        if (wid == 0) {
            // tab0: z^i, chained from exact z
            C2 tv = { 1.0f, 0.0f };
            sTab[0][0][n] = make_float2(1.0f, 0.0f);
            #pragma unroll
            for (int i = 1; i < 8; i++) {
                tv = cmul(tv, z);
                sTab[0][i][n] = make_float2(tv.r, tv.i);
            }
        } else if (wid == 1) {
            // Cd = 2*C*(e^{dtA}-1)/A
            const float sh   = __sinf(0.5f * red);
            const float numr = em1 * cy - 2.0f * sh * sh;   // e^x cos y - 1
            const float numi = ex * sy;                     // e^x sin y
            const float invd = 1.0f / (Arf * Arf + Aif * Aif);
            const float tr = (numr * Arf + numi * Aif) * invd;
            const float ti = (numi * Arf - numr * Aif) * invd;
            const float Cr = C_real[(h * NH + n) * 2 + 0];
            const float Ci = C_real[(h * NH + n) * 2 + 1];
            C2 tv = { 2.0f * (Cr * tr - Ci * ti), 2.0f * (Cr * ti + Ci * tr) };
            const C2 z8 = zpow(xr, yi, 8.0f);
            sTab[1][0][n] = make_float2(tv.r, tv.i);
            #pragma unroll
            for (int j = 1; j < 8; j++) {
                tv = cmul(tv, z8);
                sTab[1][j][n] = make_float2(tv.r, tv.i);
            }
        } else if (wid == 2) {
            const C2 z64 = zpow(xr, yi, 64.0f);
            C2 tv = { 1.0f, 0.0f };
            sTab[2][0][n] = make_float2(1.0f, 0.0f);
            #pragma unroll
            for (int i = 1; i < 8; i++) {
                tv = cmul(tv, z64);
                sTab[2][i][n] = make_float2(tv.r, tv.i);
            }
        } else {
            const C2 z512 = zpow(xr, yi, 512.0f);
            C2 tv = { 1.0f, 0.0f };
            sTab[3][0][n] = make_float2(1.0f, 0.0f);
            #pragma unroll
            for (int j = 1; j < 8; j++) {
                tv = cmul(tv, z512);
                sTab[3][j][n] = make_float2(tv.r, tv.i);
            }
        }
    }
    __syncthreads();

    // ---- B producer: thread -> (b=lane, b=lane+32) x 8 n, pure cmul ----------
    {
        const int bl = tid & 31;
        const int nb = (tid >> 5) * 8;
        const int bi = bl & 7;
        const int bj = bl >> 3;
        unsigned char* Bh = sB;
        unsigned char* Bl = sB + 64 * BSTRIDE;
        uint32_t h0v[8], l0v[8], h1v[8], l1v[8];
        #pragma unroll
        for (int j = 0; j < 8; j++) {
            const int n = nb + j;
            const float2 tc  = sTab[2][bi][n];        // z^(64*bi)
            const float2 td  = sTab[3][bj][n];        // z^(512*bj)
            const float2 td2 = sTab[3][bj + 4][n];    // z^(512*bj + 2048)
            const C2 q  = cmul(C2{ td.x,  td.y  }, C2{ tc.x, tc.y });  // z^(64*bl)
            const C2 qh = cmul(C2{ td2.x, td2.y }, C2{ tc.x, tc.y });  // z^(64*(bl+32))
            split_pack(q.r,  q.i,  h0v[j], l0v[j]);
            split_pack(qh.r, qh.i, h1v[j], l1v[j]);
        }
        const uint32_t off  = (uint32_t)(bl * BSTRIDE + 4 * nb);
        const uint32_t off2 = (uint32_t)((bl + 32) * BSTRIDE + 4 * nb);
        *(uint4*)(Bh + off)       = *(uint4*)(h0v);
        *(uint4*)(Bh + off + 16)  = *(uint4*)(h0v + 4);
        *(uint4*)(Bl + off)       = *(uint4*)(l0v);
        *(uint4*)(Bl + off + 16)  = *(uint4*)(l0v + 4);
        *(uint4*)(Bh + off2)      = *(uint4*)(h1v);
        *(uint4*)(Bh + off2 + 16) = *(uint4*)(h1v + 4);
        *(uint4*)(Bl + off2)      = *(uint4*)(l1v);
        *(uint4*)(Bl + off2 + 16) = *(uint4*)(l1v + 4);
    }
    __syncthreads();

    // ---- MMA mainloop: kt outer; B frags double-buffered over nt -------------
    const int w = tid >> 5;        // warp -> rows 16w..16w+15
    const int r = (tid >> 2) & 7;  // lane/4
    const int t = tid & 3;         // lane%4

    float d[8][4];
    #pragma unroll
    for (int nt = 0; nt < 8; nt++)
        #pragma unroll
        for (int c = 0; c < 4; c++) d[nt][c] = 0.0f;

    const unsigned char* Bh  = sB;
    const unsigned char* Blo = sB + 64 * BSTRIDE;

    #pragma unroll
    for (int kt = 0; kt < 4; kt++) {
        // A fragments for this kt from tables (2 cmul + 2 split per s)
        uint32_t Ah[4], Al[4];
        #pragma unroll
        for (int s = 0; s < 2; s++) {
            const int n = 8 * kt + t + 4 * s;
            const float2 ta  = sTab[0][r][n];          // z^r
            const float2 tb0 = sTab[1][2 * w][n];      // Cd*z^(16w)
            const float2 tb1 = sTab[1][2 * w + 1][n];  // Cd*z^(16w+8)
            const C2 p  = cmul(C2{ tb0.x, tb0.y }, C2{ ta.x, ta.y });  // Cd*z^a
            const C2 ph = cmul(C2{ tb1.x, tb1.y }, C2{ ta.x, ta.y });  // Cd*z^(a+8)
            split_pack(p.r,  -p.i,  Ah[0 + 2 * s], Al[0 + 2 * s]);
            split_pack(ph.r, -ph.i, Ah[1 + 2 * s], Al[1 + 2 * s]);
        }
        // double-buffered B fragment loads across nt
        uint32_t bh0, bh1, bl0, bl1;
        {
            const uint32_t off0 = (uint32_t)(r * BSTRIDE + 4 * t + 32 * kt);
            bh0 = *(const uint32_t*)(Bh  + off0);
            bh1 = *(const uint32_t*)(Bh  + off0 + 16);
            bl0 = *(const uint32_t*)(Blo + off0);
            bl1 = *(const uint32_t*)(Blo + off0 + 16);
        }
        #pragma unroll
        for (int nt = 0; nt < 8; nt++) {
            uint32_t nh0, nh1, nl0, nl1;
            if (nt < 7) {
                const uint32_t offn = (uint32_t)((8 * (nt + 1) + r) * BSTRIDE + 4 * t + 32 * kt);
                nh0 = *(const uint32_t*)(Bh  + offn);
                nh1 = *(const uint32_t*)(Bh  + offn + 16);
                nl0 = *(const uint32_t*)(Blo + offn);
                nl1 = *(const uint32_t*)(Blo + offn + 16);
            }
            mma16816(d[nt][0], d[nt][1], d[nt][2], d[nt][3],
                     Ah[0], Ah[1], Ah[2], Ah[3], bh0, bh1);
            mma16816(d[nt][0], d[nt][1], d[nt][2], d[nt][3],
                     Ah[0], Ah[1], Ah[2], Ah[3], bl0, bl1);
            mma16816(d[nt][0], d[nt][1], d[nt][2], d[nt][3],
                     Al[0], Al[1], Al[2], Al[3], bh0, bh1);
            if (nt < 7) { bh0 = nh0; bh1 = nh1; bl0 = nl0; bl1 = nl1; }
        }
    }
    __syncthreads();   // all B reads done before Dt overlay

    // ---- stage D[a][b] -> Dt[b][a] (pad 68 words: conflict-free writes) ------
    float (*Dt)[68] = reinterpret_cast<float(*)[68]>(sB);
    {
        const int ar = 16 * w + r;
        #pragma unroll
        for (int nt = 0; nt < 8; nt++) {
            const int bc = 8 * nt + 2 * t;
            Dt[bc    ][ar    ] = d[nt][0];
            Dt[bc + 1][ar    ] = d[nt][1];
            Dt[bc    ][ar + 8] = d[nt][2];
            Dt[bc + 1][ar + 8] = d[nt][3];
        }
    }
    __syncthreads();

    // ---- coalesced vector store: out[h][b*64+a] ------------------------------
    float* outh = out + (size_t)h * LLEN;
    #pragma unroll
    for (int it = 0; it < 8; it++) {
        const int idx = it * 512 + tid * 4;
        const float4 v = *(const float4*)&Dt[idx >> 6][idx & 63];
        *(float4*)&outh[idx] = v;
    }
}

extern "C" void kernel_launch(void* const* d_in, const int* in_sizes, int n_in,
                              void* d_out, int out_size)
{
    const float* log_dt     = (const float*)d_in[0];
    const float* C_real     = (const float*)d_in[1];
    const float* log_A_real = (const float*)d_in[2];
    const float* A_imag     = (const float*)d_in[3];
    float* out = (float*)d_out;
    s4d_mma_kernel<<<1024, 128>>>(log_dt, C_real, log_A_real, A_imag, out);
}

// round 17
// speedup vs baseline: 1.3782x; 1.1003x over previous
#include <cuda_runtime.h>
#include <cuda_fp16.h>
#include <math.h>
#include <stdint.h>

#define NH    32
#define NHP   34      // padded n-dim for tables (bank spread)
#define LLEN  4096
#define BSTRIDE 144   // bytes per b-row in smem B (32 half2 words + pad)

struct C2 { float r, i; };

static __device__ __forceinline__ C2 cmul(C2 a, C2 b) {
    return { a.r * b.r - a.i * b.i, a.r * b.i + a.i * b.r };
}

// fp32 phase reduction: exact Dekker product + 3-term Cody-Waite (R6-proven)
static __device__ __forceinline__ float reduce2pi(float yi, float lf) {
    const float INV2PI = 0.15915494309189534f;
    const float PI2_A  = 6.28125f;
    const float PI2_B  = 1.93500518798828125e-3f;
    const float PI2_C  = 3.0199159819568e-7f;
    const float p  = yi * lf;
    const float pe = fmaf(yi, lf, -p);
    const float k  = rintf(p * INV2PI);
    const float t0 = fmaf(-k, PI2_A, p);
    const float t1 = fmaf(-k, PI2_B, t0);
    return fmaf(-k, PI2_C, t1) + pe;
}

static __device__ __forceinline__ C2 zpow(float xr, float yi, float lf) {
    const float red = reduce2pi(yi, lf);
    float sf, cf;
    __sincosf(red, &sf, &cf);
    const float ef = __expf(xr * lf);
    return { ef * cf, ef * sf };
}

// split (v0,v1) into f16 hi pair + f16 lo (residual) pair
static __device__ __forceinline__ void split_pack_h(float v0, float v1,
                                                    uint32_t& hi, uint32_t& lo) {
    const __half h0 = __float2half_rn(v0);
    const __half h1 = __float2half_rn(v1);
    const float r0 = v0 - __half2float(h0);
    const float r1 = v1 - __half2float(h1);
    const __half2 H = __halves2half2(h0, h1);                    // lo16 = v0
    const __half2 L = __halves2half2(__float2half_rn(r0), __float2half_rn(r1));
    hi = *reinterpret_cast<const uint32_t*>(&H);
    lo = *reinterpret_cast<const uint32_t*>(&L);
}

static __device__ __forceinline__ void mma16816h(
    float& d0, float& d1, float& d2, float& d3,
    uint32_t a0, uint32_t a1, uint32_t a2, uint32_t a3,
    uint32_t b0, uint32_t b1)
{
    asm volatile(
        "mma.sync.aligned.m16n8k16.row.col.f32.f16.f16.f32 "
        "{%0,%1,%2,%3}, {%4,%5,%6,%7}, {%8,%9}, {%0,%1,%2,%3};"
        : "+f"(d0), "+f"(d1), "+f"(d2), "+f"(d3)
        : "r"(a0), "r"(a1), "r"(a2), "r"(a3), "r"(b0), "r"(b1));
}

__global__ __launch_bounds__(128, 8) void s4d_mma_kernel(
    const float* __restrict__ log_dt,
    const float* __restrict__ C_real,
    const float* __restrict__ log_A_real,
    const float* __restrict__ A_imag,
    float* __restrict__ out)
{
    // tables [tab][i][n]: 0: z^i, 1: Cd*z^(8j), 2: z^(64i), 3: z^(512j)
    __shared__ __align__(16) float2 sTab[4][8][NHP];               // 8704 B
    // union: B (single f16 plane, 64 rows x 144B = 9216 B) then Dt[64][68] f32 (17408 B)
    __shared__ __align__(16) unsigned char sU[64 * 68 * 4];        // 17408 B

    const int h   = blockIdx.x;
    const int tid = threadIdx.x;
    const int wid  = tid >> 5;
    const int lane = tid & 31;

    // ---- merged phase 1+2: lane n scalars (x4 redundant), warp w builds table w
    {
        const int n = lane;
        const float dt  = expf(log_dt[h]);                 // accuracy-critical
        const float Arf = -__expf(log_A_real[h * NH + n]);
        const float Aif = A_imag[h * NH + n];
        const float xr  = dt * Arf;           // matches reference f32 product
        const float yi  = dt * Aif;

        // e^x - 1, x in [-0.0503, 0): Taylor, rel tail < 3e-9
        const float em1 = xr * fmaf(xr, fmaf(xr, fmaf(xr, 1.0f/24.0f, 1.0f/6.0f), 0.5f), 1.0f);
        const float red = reduce2pi(yi, 1.0f);
        float sy, cy;
        __sincosf(red, &sy, &cy);
        const float ex = 1.0f + em1;
        const C2 z = { ex * cy, ex * sy };                 // z = e^{dtA}, free

        if (wid == 0) {
            C2 tv = { 1.0f, 0.0f };
            sTab[0][0][n] = make_float2(1.0f, 0.0f);
            #pragma unroll
            for (int i = 1; i < 8; i++) {
                tv = cmul(tv, z);
                sTab[0][i][n] = make_float2(tv.r, tv.i);
            }
        } else if (wid == 1) {
            const float sh   = __sinf(0.5f * red);
            const float numr = em1 * cy - 2.0f * sh * sh;   // e^x cos y - 1
            const float numi = ex * sy;                     // e^x sin y
            const float invd = 1.0f / (Arf * Arf + Aif * Aif);
            const float tr = (numr * Arf + numi * Aif) * invd;
            const float ti = (numi * Arf - numr * Aif) * invd;
            const float Cr = C_real[(h * NH + n) * 2 + 0];
            const float Ci = C_real[(h * NH + n) * 2 + 1];
            C2 tv = { 2.0f * (Cr * tr - Ci * ti), 2.0f * (Cr * ti + Ci * tr) };
            const C2 z8 = zpow(xr, yi, 8.0f);
            sTab[1][0][n] = make_float2(tv.r, tv.i);
            #pragma unroll
            for (int j = 1; j < 8; j++) {
                tv = cmul(tv, z8);
                sTab[1][j][n] = make_float2(tv.r, tv.i);
            }
        } else if (wid == 2) {
            const C2 z64 = zpow(xr, yi, 64.0f);
            C2 tv = { 1.0f, 0.0f };
            sTab[2][0][n] = make_float2(1.0f, 0.0f);
            #pragma unroll
            for (int i = 1; i < 8; i++) {
                tv = cmul(tv, z64);
                sTab[2][i][n] = make_float2(tv.r, tv.i);
            }
        } else {
            const C2 z512 = zpow(xr, yi, 512.0f);
            C2 tv = { 1.0f, 0.0f };
            sTab[3][0][n] = make_float2(1.0f, 0.0f);
            #pragma unroll
            for (int j = 1; j < 8; j++) {
                tv = cmul(tv, z512);
                sTab[3][j][n] = make_float2(tv.r, tv.i);
            }
        }
    }
    __syncthreads();

    // ---- B producer: thread -> (b=lane, b=lane+32) x 8 n, single f16 plane ---
    {
        const int bl = tid & 31;
        const int nb = (tid >> 5) * 8;
        const int bi = bl & 7;
        const int bj = bl >> 3;
        unsigned char* Bp = sU;
        uint32_t h0v[8], h1v[8];
        #pragma unroll
        for (int j = 0; j < 8; j++) {
            const int n = nb + j;
            const float2 tc  = sTab[2][bi][n];        // z^(64*bi)
            const float2 td  = sTab[3][bj][n];        // z^(512*bj)
            const float2 td2 = sTab[3][bj + 4][n];    // z^(512*bj + 2048)
            const C2 q  = cmul(C2{ td.x,  td.y  }, C2{ tc.x, tc.y });  // z^(64*bl)
            const C2 qh = cmul(C2{ td2.x, td2.y }, C2{ tc.x, tc.y });  // z^(64*(bl+32))
            const __half2 q2  = __floats2half2_rn(q.r,  q.i);   // lo = Qr
            const __half2 qh2 = __floats2half2_rn(qh.r, qh.i);
            h0v[j] = *reinterpret_cast<const uint32_t*>(&q2);
            h1v[j] = *reinterpret_cast<const uint32_t*>(&qh2);
        }
        const uint32_t off  = (uint32_t)(bl * BSTRIDE + 4 * nb);
        const uint32_t off2 = (uint32_t)((bl + 32) * BSTRIDE + 4 * nb);
        *(uint4*)(Bp + off)       = *(uint4*)(h0v);
        *(uint4*)(Bp + off + 16)  = *(uint4*)(h0v + 4);
        *(uint4*)(Bp + off2)      = *(uint4*)(h1v);
        *(uint4*)(Bp + off2 + 16) = *(uint4*)(h1v + 4);
    }
    __syncthreads();

    // ---- MMA mainloop: kt outer; 2 passes (A hi/lo), B single ----------------
    const int w = tid >> 5;        // warp -> rows 16w..16w+15
    const int r = (tid >> 2) & 7;  // lane/4
    const int t = tid & 3;         // lane%4

    float d[8][4];
    #pragma unroll
    for (int nt = 0; nt < 8; nt++)
        #pragma unroll
        for (int c = 0; c < 4; c++) d[nt][c] = 0.0f;

    const unsigned char* Bp = sU;

    #pragma unroll
    for (int kt = 0; kt < 4; kt++) {
        // A fragments for this kt from tables (2 cmul + 2 f16 splits per s)
        uint32_t Ah[4], Al[4];
        #pragma unroll
        for (int s = 0; s < 2; s++) {
            const int n = 8 * kt + t + 4 * s;
            const float2 ta  = sTab[0][r][n];          // z^r
            const float2 tb0 = sTab[1][2 * w][n];      // Cd*z^(16w)
            const float2 tb1 = sTab[1][2 * w + 1][n];  // Cd*z^(16w+8)
            const C2 p  = cmul(C2{ tb0.x, tb0.y }, C2{ ta.x, ta.y });  // Cd*z^a
            const C2 ph = cmul(C2{ tb1.x, tb1.y }, C2{ ta.x, ta.y });  // Cd*z^(a+8)
            split_pack_h(p.r,  -p.i,  Ah[0 + 2 * s], Al[0 + 2 * s]);
            split_pack_h(ph.r, -ph.i, Ah[1 + 2 * s], Al[1 + 2 * s]);
        }
        // double-buffered B fragment loads across nt
        uint32_t bh0, bh1;
        {
            const uint32_t off0 = (uint32_t)(r * BSTRIDE + 4 * t + 32 * kt);
            bh0 = *(const uint32_t*)(Bp + off0);
            bh1 = *(const uint32_t*)(Bp + off0 + 16);
        }
        #pragma unroll
        for (int nt = 0; nt < 8; nt++) {
            uint32_t nh0, nh1;
            if (nt < 7) {
                const uint32_t offn = (uint32_t)((8 * (nt + 1) + r) * BSTRIDE + 4 * t + 32 * kt);
                nh0 = *(const uint32_t*)(Bp + offn);
                nh1 = *(const uint32_t*)(Bp + offn + 16);
            }
            mma16816h(d[nt][0], d[nt][1], d[nt][2], d[nt][3],
                      Ah[0], Ah[1], Ah[2], Ah[3], bh0, bh1);
            mma16816h(d[nt][0], d[nt][1], d[nt][2], d[nt][3],
                      Al[0], Al[1], Al[2], Al[3], bh0, bh1);
            if (nt < 7) { bh0 = nh0; bh1 = nh1; }
        }
    }
    __syncthreads();   // all B reads done before Dt overlay

    // ---- stage D[a][b] -> Dt[b][a] (pad 68 words: conflict-free writes) ------
    float (*Dt)[68] = reinterpret_cast<float(*)[68]>(sU);
    {
        const int ar = 16 * w + r;
        #pragma unroll
        for (int nt = 0; nt < 8; nt++) {
            const int bc = 8 * nt + 2 * t;
            Dt[bc    ][ar    ] = d[nt][0];
            Dt[bc + 1][ar    ] = d[nt][1];
            Dt[bc    ][ar + 8] = d[nt][2];
            Dt[bc + 1][ar + 8] = d[nt][3];
        }
    }
    __syncthreads();

    // ---- coalesced vector store: out[h][b*64+a] ------------------------------
    float* outh = out + (size_t)h * LLEN;
    #pragma unroll
    for (int it = 0; it < 8; it++) {
        const int idx = it * 512 + tid * 4;
        const float4 v = *(const float4*)&Dt[idx >> 6][idx & 63];
        *(float4*)&outh[idx] = v;
    }
}

extern "C" void kernel_launch(void* const* d_in, const int* in_sizes, int n_in,
                              void* d_out, int out_size)
{
    const float* log_dt     = (const float*)d_in[0];
    const float* C_real     = (const float*)d_in[1];
    const float* log_A_real = (const float*)d_in[2];
    const float* A_imag     = (const float*)d_in[3];
    float* out = (float*)d_out;
    s4d_mma_kernel<<<1024, 128>>>(log_dt, C_real, log_A_real, A_imag, out);
}